// round 1
// baseline (speedup 1.0000x reference)
#include <cuda_runtime.h>

#define NTOK 65536
#define CDIM 180
#define NH 6
#define HD 30
#define QKVC 540

// Scratch (device globals — no allocation allowed)
__device__ float g_xn[(size_t)NTOK * CDIM];
__device__ float g_qkv[(size_t)NTOK * QKVC];   // [tok][0:180 q | 180:360 k | 360:540 v]
__device__ float g_att[(size_t)NTOK * CDIM];

// ---------------- LayerNorm: one warp per row ----------------
__global__ void ln_kernel(const float* __restrict__ x, const float* __restrict__ w,
                          const float* __restrict__ b, float* __restrict__ out) {
    int row  = blockIdx.x * 8 + (threadIdx.x >> 5);
    int lane = threadIdx.x & 31;
    const float* xr = x + (size_t)row * CDIM;
    float v[6];
    float s = 0.f, s2 = 0.f;
#pragma unroll
    for (int i = 0; i < 6; i++) {
        int d = lane + 32 * i;
        float val = (d < CDIM) ? xr[d] : 0.f;
        v[i] = val; s += val; s2 += val * val;
    }
#pragma unroll
    for (int o = 16; o; o >>= 1) {
        s  += __shfl_xor_sync(0xffffffffu, s, o);
        s2 += __shfl_xor_sync(0xffffffffu, s2, o);
    }
    float mu  = s * (1.f / CDIM);
    float var = s2 * (1.f / CDIM) - mu * mu;
    float rs  = rsqrtf(var + 1e-5f);
    float* orow = out + (size_t)row * CDIM;
#pragma unroll
    for (int i = 0; i < 6; i++) {
        int d = lane + 32 * i;
        if (d < CDIM) orow[d] = (v[i] - mu) * rs * w[d] + b[d];
    }
}

// ---------------- Generic fp32 GEMM: C[M,N] = A[M,180] @ B[180,N] + bias (+res) ----------------
// 64x64 tile, BK=20 (180 = 9*20), 256 threads, 4x4 microtile.
__global__ __launch_bounds__(256) void gemm_kernel(
    const float* __restrict__ A, const float* __restrict__ B,
    const float* __restrict__ bias, const float* __restrict__ res,
    float* __restrict__ C, int N, int ldc) {
    __shared__ float As[20][64];
    __shared__ float Bs[20][64];
    int tx = threadIdx.x, ty = threadIdx.y;
    int li = ty * 16 + tx;
    int rowbase = blockIdx.y * 64;
    int nbase   = blockIdx.x * 64;
    float acc[4][4] = {};
    for (int k0 = 0; k0 < 180; k0 += 20) {
#pragma unroll
        for (int e = 0; e < 5; e++) {
            int idx = li + e * 256;
            int r = idx / 20, kk = idx - r * 20;
            As[kk][r] = A[(size_t)(rowbase + r) * 180 + k0 + kk];
            int rb = idx >> 6, cb = idx & 63;
            int col = nbase + cb;
            Bs[rb][cb] = (col < N) ? B[(size_t)(k0 + rb) * N + col] : 0.f;
        }
        __syncthreads();
#pragma unroll
        for (int kk = 0; kk < 20; kk++) {
            float4 a  = *(const float4*)&As[kk][ty * 4];
            float4 bv = *(const float4*)&Bs[kk][tx * 4];
            float av[4] = {a.x, a.y, a.z, a.w};
            float bb[4] = {bv.x, bv.y, bv.z, bv.w};
#pragma unroll
            for (int i = 0; i < 4; i++)
#pragma unroll
                for (int j = 0; j < 4; j++)
                    acc[i][j] = fmaf(av[i], bb[j], acc[i][j]);
        }
        __syncthreads();
    }
#pragma unroll
    for (int i = 0; i < 4; i++) {
        int row = rowbase + ty * 4 + i;
#pragma unroll
        for (int j = 0; j < 4; j++) {
            int col = nbase + tx * 4 + j;
            if (col < N) {
                float vv = acc[i][j] + bias[col];
                if (res) vv += res[(size_t)row * N + col];
                C[(size_t)row * ldc + col] = vv;
            }
        }
    }
}

// ---------------- Attention: one block per (head, window) ----------------
// 128 threads, 2 queries/thread (256 queries), 576 keys in 6 chunks of 96.
// Online softmax with rare rescale branch. OOB (padded) keys -> kv bias.
__global__ __launch_bounds__(128) void attn_kernel(const float* __restrict__ qkv,
                                                   const float* __restrict__ kv_b,
                                                   float* __restrict__ att) {
    int h  = blockIdx.x;
    int wi = blockIdx.y;
    int wh = wi >> 4, ww = wi & 15;
    int tid = threadIdx.x;
    __shared__ float ks[96][32];
    __shared__ float vs[96][32];

    const float scale = 0.18257418583505536f;  // 30^-0.5

    int q0i = tid, q1i = tid + 128;
    int tok0 = (wh * 16 + (q0i >> 4)) * 256 + ww * 16 + (q0i & 15);
    int tok1 = (wh * 16 + (q1i >> 4)) * 256 + ww * 16 + (q1i & 15);

    float q0[HD], q1[HD], o0[HD], o1[HD];
#pragma unroll
    for (int d = 0; d < HD; d++) {
        q0[d] = qkv[(size_t)tok0 * QKVC + h * HD + d] * scale;
        q1[d] = qkv[(size_t)tok1 * QKVC + h * HD + d] * scale;
        o0[d] = 0.f; o1[d] = 0.f;
    }
    float m0 = -1e30f, m1 = -1e30f, s0 = 0.f, s1 = 0.f;

    for (int c = 0; c < 6; c++) {
        __syncthreads();
        for (int idx = tid; idx < 96 * HD; idx += 128) {
            int j = idx / HD, d = idx - j * HD;
            int kk = c * 96 + j;            // key index within 24x24 window
            int r = kk / 24, cc = kk - r * 24;
            int gh = wh * 16 - 4 + r, gw = ww * 16 - 4 + cc;
            float kval, vval;
            if ((unsigned)gh < 256u && (unsigned)gw < 256u) {
                size_t t = (size_t)(gh * 256 + gw) * QKVC;
                kval = qkv[t + CDIM + h * HD + d];
                vval = qkv[t + 2 * CDIM + h * HD + d];
            } else {
                kval = kv_b[h * HD + d];         // feature zero-pad -> kv = bias
                vval = kv_b[CDIM + h * HD + d];
            }
            ks[j][d] = kval;
            vs[j][d] = vval;
        }
        __syncthreads();
#pragma unroll 1
        for (int j = 0; j < 96; j++) {
            float d0 = 0.f, d1 = 0.f;
#pragma unroll
            for (int d = 0; d < HD; d++) {
                float kd = ks[j][d];
                d0 = fmaf(q0[d], kd, d0);
                d1 = fmaf(q1[d], kd, d1);
            }
            if (d0 > m0) {
                float rr = __expf(m0 - d0); m0 = d0; s0 *= rr;
#pragma unroll
                for (int d = 0; d < HD; d++) o0[d] *= rr;
            }
            if (d1 > m1) {
                float rr = __expf(m1 - d1); m1 = d1; s1 *= rr;
#pragma unroll
                for (int d = 0; d < HD; d++) o1[d] *= rr;
            }
            float p0 = __expf(d0 - m0); s0 += p0;
            float p1 = __expf(d1 - m1); s1 += p1;
#pragma unroll
            for (int d = 0; d < HD; d++) {
                float vd = vs[j][d];
                o0[d] = fmaf(p0, vd, o0[d]);
                o1[d] = fmaf(p1, vd, o1[d]);
            }
        }
    }
    float r0 = 1.f / s0, r1 = 1.f / s1;
#pragma unroll
    for (int d = 0; d < HD; d++) {
        att[(size_t)tok0 * CDIM + h * HD + d] = o0[d] * r0;
        att[(size_t)tok1 * CDIM + h * HD + d] = o1[d] * r1;
    }
}

extern "C" void kernel_launch(void* const* d_in, const int* in_sizes, int n_in,
                              void* d_out, int out_size) {
    const float* x      = (const float*)d_in[0];
    const float* norm_w = (const float*)d_in[1];
    const float* norm_b = (const float*)d_in[2];
    const float* q_w    = (const float*)d_in[3];
    const float* q_b    = (const float*)d_in[4];
    const float* kv_w   = (const float*)d_in[5];
    const float* kv_b   = (const float*)d_in[6];
    const float* proj_w = (const float*)d_in[7];
    const float* proj_b = (const float*)d_in[8];
    float* out = (float*)d_out;
    (void)in_sizes; (void)n_in; (void)out_size;

    float *xn, *qkv, *att;
    cudaGetSymbolAddress((void**)&xn,  g_xn);
    cudaGetSymbolAddress((void**)&qkv, g_qkv);
    cudaGetSymbolAddress((void**)&att, g_att);

    dim3 gblk(16, 16);

    // 1. LayerNorm
    ln_kernel<<<NTOK / 8, 256>>>(x, norm_w, norm_b, xn);
    // 2. q projection -> qkv[:, 0:180]
    gemm_kernel<<<dim3(3, NTOK / 64), gblk>>>(xn, q_w, q_b, nullptr, qkv, 180, QKVC);
    // 3. kv projection -> qkv[:, 180:540]
    gemm_kernel<<<dim3(6, NTOK / 64), gblk>>>(xn, kv_w, kv_b, nullptr, qkv + CDIM, 360, QKVC);
    // 4. windowed overlapping attention
    attn_kernel<<<dim3(NH, 256), 128>>>(qkv, kv_b, att);
    // 5. output projection + bias + residual -> d_out
    gemm_kernel<<<dim3(3, NTOK / 64), gblk>>>(att, proj_w, proj_b, x, out, 180, CDIM);
}